// round 3
// baseline (speedup 1.0000x reference)
#include <cuda_runtime.h>
#include <cuda_bf16.h>

#define N_NODES 8192
#define FIN 128
#define FOUT 64
#define EMAX 262144

// Scratch (allocation-free rule: __device__ globals)
__device__ int   g_cnt[N_NODES];     // in-degree (excl. self loop)
__device__ int   g_off[N_NODES];     // CSR offsets (exclusive scan of cnt)
__device__ int   g_cur[N_NODES];     // scatter cursors
__device__ int   g_srcs[EMAX];       // src ids grouped by dst
__device__ float g_dinv[N_NODES];
__device__ float g_h[N_NODES * FOUT];
__device__ float g_z[N_NODES * FOUT];

// ---------------------------------------------------------------- init counters
__global__ void k_init() {
    int i = blockIdx.x * blockDim.x + threadIdx.x;
    if (i < N_NODES) g_cnt[i] = 0;
}

// ---------------------------------------------------------------- count in-degree per dst
__global__ void k_count(const int* __restrict__ ei, int E) {
    int e = blockIdx.x * blockDim.x + threadIdx.x;
    if (e < E) {
        int d = ei[E + e];               // edge_index[1] = dst (int32!)
        atomicAdd(&g_cnt[d], 1);
    }
}

// ---------------------------------------------------------------- exclusive scan (1 block, 1024 thr)
__global__ void k_scan() {
    __shared__ int sA[1024], sB[1024];
    int t = threadIdx.x;
    int base = t * 8;
    int v[8];
    int sum = 0;
#pragma unroll
    for (int i = 0; i < 8; i++) { v[i] = g_cnt[base + i]; sum += v[i]; }
    sA[t] = sum;
    __syncthreads();
    int* src = sA; int* dst = sB;
    for (int off = 1; off < 1024; off <<= 1) {
        int val = src[t];
        if (t >= off) val += src[t - off];
        dst[t] = val;
        __syncthreads();
        int* tmp = src; src = dst; dst = tmp;
    }
    int excl = src[t] - sum;
    int run = excl;
#pragma unroll
    for (int i = 0; i < 8; i++) {
        g_off[base + i] = run;
        run += v[i];
        g_cur[base + i] = 0;
        g_dinv[base + i] = rsqrtf((float)(v[i] + 1));   // +1 self loop
    }
}

// ---------------------------------------------------------------- scatter srcs into CSR
__global__ void k_scatter(const int* __restrict__ ei, int E) {
    int e = blockIdx.x * blockDim.x + threadIdx.x;
    if (e < E) {
        int s = ei[e];
        int d = ei[E + e];
        int pos = g_off[d] + atomicAdd(&g_cur[d], 1);
        g_srcs[pos] = s;
    }
}

// ---------------------------------------------------------------- h = x^T @ W   (x: [FIN, N] row-major)
__global__ void k_h(const float* __restrict__ x, const float* __restrict__ W) {
    int gid = blockIdx.x * blockDim.x + threadIdx.x;   // N * 16
    int n = gid >> 4, q = gid & 15;                    // q -> 4 output features
    const float4* W4 = (const float4*)W;               // W[f][o], row = 16 float4
    float4 acc = make_float4(0.f, 0.f, 0.f, 0.f);
#pragma unroll 4
    for (int f = 0; f < FIN; f++) {
        float xv = __ldg(&x[f * N_NODES + n]);
        float4 w = __ldg(&W4[f * 16 + q]);
        acc.x = fmaf(xv, w.x, acc.x);
        acc.y = fmaf(xv, w.y, acc.y);
        acc.z = fmaf(xv, w.z, acc.z);
        acc.w = fmaf(xv, w.w, acc.w);
    }
    *(float4*)&g_h[n * FOUT + q * 4] = acc;
}

// ---------------------------------------------------------------- atomic-free gather: warp per dst
__global__ void k_gather(const float* __restrict__ b) {
    int warp = (blockIdx.x * blockDim.x + threadIdx.x) >> 5;
    int lane = threadIdx.x & 31;
    if (warp >= N_NODES) return;
    int d = warp;
    float dd = g_dinv[d];
    int beg = g_off[d];
    int cnt = g_cnt[d];
    // self-loop term: dinv[d]^2 * h[d], folded as dd*(dd*h[d])
    float a0 = dd * g_h[d * FOUT + lane];
    float a1 = dd * g_h[d * FOUT + lane + 32];
    int j = 0;
    for (; j + 2 <= cnt; j += 2) {
        int s0 = __ldg(&g_srcs[beg + j]);
        int s1 = __ldg(&g_srcs[beg + j + 1]);
        float ds0 = g_dinv[s0];
        float ds1 = g_dinv[s1];
        a0 = fmaf(ds0, g_h[s0 * FOUT + lane], a0);
        a1 = fmaf(ds0, g_h[s0 * FOUT + lane + 32], a1);
        a0 = fmaf(ds1, g_h[s1 * FOUT + lane], a0);
        a1 = fmaf(ds1, g_h[s1 * FOUT + lane + 32], a1);
    }
    if (j < cnt) {
        int s0 = __ldg(&g_srcs[beg + j]);
        float ds0 = g_dinv[s0];
        a0 = fmaf(ds0, g_h[s0 * FOUT + lane], a0);
        a1 = fmaf(ds0, g_h[s0 * FOUT + lane + 32], a1);
    }
    g_z[d * FOUT + lane]      = fmaf(dd, a0, b[lane]);
    g_z[d * FOUT + lane + 32] = fmaf(dd, a1, b[lane + 32]);
}

// ---------------------------------------------------------------- sigmoid(z z^T), symmetric tiling
__device__ __forceinline__ float sigmoidf(float v) {
    return __fdividef(1.0f, 1.0f + __expf(-v));
}

__global__ void __launch_bounds__(256, 2) k_gemm_sym(float* __restrict__ out) {
    const int bi = blockIdx.y, bj = blockIdx.x;
    if (bj < bi) return;
    const int i0 = bi * 128, j0 = bj * 128;

    __shared__ float As[32][130];   // [k][row]; stride 130: even -> 8B-aligned pairs
    __shared__ float Bs[32][130];

    const int tid = threadIdx.x;
    const int tx = tid & 15;        // col group (8 cols)
    const int ty = tid >> 4;        // row group (8 rows)

    unsigned long long acc2[8][4];  // 8 rows x 4 col-pairs, packed f32x2
#pragma unroll
    for (int r = 0; r < 8; r++)
#pragma unroll
        for (int cp = 0; cp < 4; cp++) acc2[r][cp] = 0ull;

    for (int kc = 0; kc < FOUT; kc += 32) {
#pragma unroll
        for (int it = 0; it < 4; it++) {
            int idx = tid + it * 256;          // 0..1023
            int row = idx >> 3;
            int c4 = idx & 7;                  // float4 within 32-wide k chunk
            float4 v = *(const float4*)&g_z[(i0 + row) * FOUT + kc + c4 * 4];
            As[c4 * 4 + 0][row] = v.x;
            As[c4 * 4 + 1][row] = v.y;
            As[c4 * 4 + 2][row] = v.z;
            As[c4 * 4 + 3][row] = v.w;
            float4 u = *(const float4*)&g_z[(j0 + row) * FOUT + kc + c4 * 4];
            Bs[c4 * 4 + 0][row] = u.x;
            Bs[c4 * 4 + 1][row] = u.y;
            Bs[c4 * 4 + 2][row] = u.z;
            Bs[c4 * 4 + 3][row] = u.w;
        }
        __syncthreads();

#pragma unroll
        for (int k = 0; k < 32; k++) {
            unsigned long long b2[4];
            const unsigned long long* bp =
                (const unsigned long long*)&Bs[k][tx * 8];   // even stride -> 8B aligned
#pragma unroll
            for (int cp = 0; cp < 4; cp++) b2[cp] = bp[cp];
#pragma unroll
            for (int r = 0; r < 8; r++) {
                float av = As[k][ty * 8 + r];
                unsigned long long a2;
                asm("mov.b64 %0, {%1, %1};" : "=l"(a2) : "f"(av));
#pragma unroll
                for (int cp = 0; cp < 4; cp++) {
                    asm("fma.rn.f32x2 %0, %1, %2, %0;"
                        : "+l"(acc2[r][cp]) : "l"(a2), "l"(b2[cp]));
                }
            }
        }
        __syncthreads();
    }

    // epilogue: unpack + sigmoid
    float s[8][8];
#pragma unroll
    for (int r = 0; r < 8; r++)
#pragma unroll
        for (int cp = 0; cp < 4; cp++) {
            float lo, hi;
            asm("mov.b64 {%0, %1}, %2;" : "=f"(lo), "=f"(hi) : "l"(acc2[r][cp]));
            s[r][cp * 2 + 0] = sigmoidf(lo);
            s[r][cp * 2 + 1] = sigmoidf(hi);
        }

    // direct tile
#pragma unroll
    for (int r = 0; r < 8; r++) {
        int row = i0 + ty * 8 + r;
        float4* p = (float4*)&out[row * N_NODES + j0 + tx * 8];
        p[0] = make_float4(s[r][0], s[r][1], s[r][2], s[r][3]);
        p[1] = make_float4(s[r][4], s[r][5], s[r][6], s[r][7]);
    }
    // mirrored tile
    if (bi != bj) {
#pragma unroll
        for (int c = 0; c < 8; c++) {
            int row = j0 + tx * 8 + c;
            float4* p = (float4*)&out[row * N_NODES + i0 + ty * 8];
            p[0] = make_float4(s[0][c], s[1][c], s[2][c], s[3][c]);
            p[1] = make_float4(s[4][c], s[5][c], s[6][c], s[7][c]);
        }
    }
}

// ----------------------------------------------------------------
extern "C" void kernel_launch(void* const* d_in, const int* in_sizes, int n_in,
                              void* d_out, int out_size) {
    const float* x  = (const float*)d_in[0];       // [128, 8192]
    const int*   ei = (const int*)d_in[1];         // [2, E] int32 (JAX x64 off!)
    const float* W  = (const float*)d_in[2];       // [128, 64]
    const float* b  = (const float*)d_in[3];       // [64]
    float* out = (float*)d_out;                    // [8192, 8192]
    const int E = in_sizes[1] / 2;

    k_init<<<(N_NODES + 255) / 256, 256>>>();
    k_count<<<(E + 255) / 256, 256>>>(ei, E);
    k_scan<<<1, 1024>>>();
    k_h<<<(N_NODES * 16) / 256, 256>>>(x, W);
    k_scatter<<<(E + 255) / 256, 256>>>(ei, E);
    k_gather<<<(N_NODES * 32) / 256, 256>>>(b);

    dim3 grid(N_NODES / 128, N_NODES / 128);
    k_gemm_sym<<<grid, 256>>>(out);
}

// round 4
// speedup vs baseline: 1.0500x; 1.0500x over previous
#include <cuda_runtime.h>
#include <cuda_bf16.h>

#define N_NODES 8192
#define FIN 128
#define FOUT 64
#define EMAX 262144

// Scratch (allocation-free rule: __device__ globals)
__device__ int   g_cnt[N_NODES];
__device__ int   g_off[N_NODES];
__device__ int   g_cur[N_NODES];
__device__ int   g_srcs[EMAX];
__device__ float g_dinv[N_NODES];
__device__ float g_h[N_NODES * FOUT];
__device__ float g_z[N_NODES * FOUT];

// ---------------------------------------------------------------- init counters
__global__ void k_init() {
    int i = blockIdx.x * blockDim.x + threadIdx.x;
    if (i < N_NODES) g_cnt[i] = 0;
}

// ---------------------------------------------------------------- count in-degree per dst
__global__ void k_count(const int* __restrict__ ei, int E) {
    int e = blockIdx.x * blockDim.x + threadIdx.x;
    if (e < E) atomicAdd(&g_cnt[ei[E + e]], 1);
}

// ---------------------------------------------------------------- exclusive scan (1 block)
__global__ void k_scan() {
    __shared__ int sA[1024], sB[1024];
    int t = threadIdx.x;
    int base = t * 8;
    int v[8];
    int sum = 0;
#pragma unroll
    for (int i = 0; i < 8; i++) { v[i] = g_cnt[base + i]; sum += v[i]; }
    sA[t] = sum;
    __syncthreads();
    int* src = sA; int* dst = sB;
    for (int off = 1; off < 1024; off <<= 1) {
        int val = src[t];
        if (t >= off) val += src[t - off];
        dst[t] = val;
        __syncthreads();
        int* tmp = src; src = dst; dst = tmp;
    }
    int excl = src[t] - sum;
    int run = excl;
#pragma unroll
    for (int i = 0; i < 8; i++) {
        g_off[base + i] = run;
        run += v[i];
        g_cur[base + i] = 0;
        g_dinv[base + i] = rsqrtf((float)(v[i] + 1));   // +1 self loop
    }
}

// ---------------------------------------------------------------- scatter srcs into CSR
__global__ void k_scatter(const int* __restrict__ ei, int E) {
    int e = blockIdx.x * blockDim.x + threadIdx.x;
    if (e < E) {
        int s = ei[e];
        int d = ei[E + e];
        int pos = g_off[d] + atomicAdd(&g_cur[d], 1);
        g_srcs[pos] = s;
    }
}

// ---------------------------------------------------------------- h = x^T @ W : warp per node
__global__ void k_h(const float* __restrict__ x, const float* __restrict__ W) {
    int warp = (blockIdx.x * blockDim.x + threadIdx.x) >> 5;
    int lane = threadIdx.x & 31;
    if (warp >= N_NODES) return;
    float a0 = 0.f, a1 = 0.f;
#pragma unroll 8
    for (int f = 0; f < FIN; f++) {
        float xv = __ldg(&x[f * N_NODES + warp]);            // warp-broadcast
        a0 = fmaf(xv, __ldg(&W[f * FOUT + lane]), a0);       // coalesced, L1-hot
        a1 = fmaf(xv, __ldg(&W[f * FOUT + lane + 32]), a1);
    }
    g_h[warp * FOUT + lane]      = a0;
    g_h[warp * FOUT + lane + 32] = a1;
}

// ---------------------------------------------------------------- atomic-free gather: warp per dst
__global__ void k_gather(const float* __restrict__ b) {
    int warp = (blockIdx.x * blockDim.x + threadIdx.x) >> 5;
    int lane = threadIdx.x & 31;
    if (warp >= N_NODES) return;
    int d = warp;
    float dd = g_dinv[d];
    int beg = g_off[d];
    int cnt = g_cnt[d];
    float a0 = dd * g_h[d * FOUT + lane];                    // self loop
    float a1 = dd * g_h[d * FOUT + lane + 32];
    int j = 0;
    for (; j + 2 <= cnt; j += 2) {
        int s0 = __ldg(&g_srcs[beg + j]);
        int s1 = __ldg(&g_srcs[beg + j + 1]);
        float ds0 = __ldg(&g_dinv[s0]);
        float ds1 = __ldg(&g_dinv[s1]);
        a0 = fmaf(ds0, __ldg(&g_h[s0 * FOUT + lane]), a0);
        a1 = fmaf(ds0, __ldg(&g_h[s0 * FOUT + lane + 32]), a1);
        a0 = fmaf(ds1, __ldg(&g_h[s1 * FOUT + lane]), a0);
        a1 = fmaf(ds1, __ldg(&g_h[s1 * FOUT + lane + 32]), a1);
    }
    if (j < cnt) {
        int s0 = __ldg(&g_srcs[beg + j]);
        float ds0 = __ldg(&g_dinv[s0]);
        a0 = fmaf(ds0, __ldg(&g_h[s0 * FOUT + lane]), a0);
        a1 = fmaf(ds0, __ldg(&g_h[s0 * FOUT + lane + 32]), a1);
    }
    g_z[d * FOUT + lane]      = fmaf(dd, a0, b[lane]);
    g_z[d * FOUT + lane + 32] = fmaf(dd, a1, b[lane + 32]);
}

// ---------------------------------------------------------------- sigmoid(z z^T), symmetric tiling
__device__ __forceinline__ float sigmoid_tanh(float v) {
    float t;
    asm("tanh.approx.f32 %0, %1;" : "=f"(t) : "f"(0.5f * v));
    return fmaf(0.5f, t, 0.5f);
}

__global__ void __launch_bounds__(256, 2) k_gemm_sym(float* __restrict__ out) {
    const int bi = blockIdx.y, bj = blockIdx.x;
    if (bj < bi) return;
    const int i0 = bi * 128, j0 = bj * 128;

    __shared__ float As[32][132];   // [k][row]; stride 132: 16B-aligned rows for LDS.128
    __shared__ float Bs[32][132];

    const int tid = threadIdx.x;
    const int tx = tid & 15;
    const int ty = tid >> 4;

    unsigned long long acc2[8][4];  // 8 rows x 4 col-pairs, packed f32x2
#pragma unroll
    for (int r = 0; r < 8; r++)
#pragma unroll
        for (int cp = 0; cp < 4; cp++) acc2[r][cp] = 0ull;

    for (int kc = 0; kc < FOUT; kc += 32) {
#pragma unroll
        for (int it = 0; it < 4; it++) {
            int idx = tid + it * 256;
            int row = idx >> 3;
            int c4 = idx & 7;
            float4 v = *(const float4*)&g_z[(i0 + row) * FOUT + kc + c4 * 4];
            As[c4 * 4 + 0][row] = v.x;
            As[c4 * 4 + 1][row] = v.y;
            As[c4 * 4 + 2][row] = v.z;
            As[c4 * 4 + 3][row] = v.w;
            float4 u = *(const float4*)&g_z[(j0 + row) * FOUT + kc + c4 * 4];
            Bs[c4 * 4 + 0][row] = u.x;
            Bs[c4 * 4 + 1][row] = u.y;
            Bs[c4 * 4 + 2][row] = u.z;
            Bs[c4 * 4 + 3][row] = u.w;
        }
        __syncthreads();

#pragma unroll
        for (int k = 0; k < 32; k++) {
            // A rows: 2x LDS.128 (broadcast across tx)
            float4 aL = *(const float4*)&As[k][ty * 8];
            float4 aH = *(const float4*)&As[k][ty * 8 + 4];
            // B col-pairs: 2x LDS.128, reinterpret as packed f32x2 operands
            ulonglong2 bL = *(const ulonglong2*)&Bs[k][tx * 8];
            ulonglong2 bH = *(const ulonglong2*)&Bs[k][tx * 8 + 4];
            unsigned long long b2[4] = { bL.x, bL.y, bH.x, bH.y };
            float a[8] = { aL.x, aL.y, aL.z, aL.w, aH.x, aH.y, aH.z, aH.w };
#pragma unroll
            for (int r = 0; r < 8; r++) {
                unsigned long long a2;
                asm("mov.b64 %0, {%1, %1};" : "=l"(a2) : "f"(a[r]));
#pragma unroll
                for (int cp = 0; cp < 4; cp++) {
                    asm("fma.rn.f32x2 %0, %1, %2, %0;"
                        : "+l"(acc2[r][cp]) : "l"(a2), "l"(b2[cp]));
                }
            }
        }
        __syncthreads();
    }

    // epilogue: unpack + sigmoid (tanh form: 1 MUFU each)
    float s[8][8];
#pragma unroll
    for (int r = 0; r < 8; r++)
#pragma unroll
        for (int cp = 0; cp < 4; cp++) {
            float lo, hi;
            asm("mov.b64 {%0, %1}, %2;" : "=f"(lo), "=f"(hi) : "l"(acc2[r][cp]));
            s[r][cp * 2 + 0] = sigmoid_tanh(lo);
            s[r][cp * 2 + 1] = sigmoid_tanh(hi);
        }

    // direct tile
#pragma unroll
    for (int r = 0; r < 8; r++) {
        int row = i0 + ty * 8 + r;
        float4* p = (float4*)&out[row * N_NODES + j0 + tx * 8];
        p[0] = make_float4(s[r][0], s[r][1], s[r][2], s[r][3]);
        p[1] = make_float4(s[r][4], s[r][5], s[r][6], s[r][7]);
    }
    // mirrored tile
    if (bi != bj) {
#pragma unroll
        for (int c = 0; c < 8; c++) {
            int row = j0 + tx * 8 + c;
            float4* p = (float4*)&out[row * N_NODES + i0 + ty * 8];
            p[0] = make_float4(s[0][c], s[1][c], s[2][c], s[3][c]);
            p[1] = make_float4(s[4][c], s[5][c], s[6][c], s[7][c]);
        }
    }
}

// ----------------------------------------------------------------
extern "C" void kernel_launch(void* const* d_in, const int* in_sizes, int n_in,
                              void* d_out, int out_size) {
    const float* x  = (const float*)d_in[0];       // [128, 8192]
    const int*   ei = (const int*)d_in[1];         // [2, E] int32
    const float* W  = (const float*)d_in[2];       // [128, 64]
    const float* b  = (const float*)d_in[3];       // [64]
    float* out = (float*)d_out;                    // [8192, 8192]
    const int E = in_sizes[1] / 2;

    k_init<<<(N_NODES + 255) / 256, 256>>>();
    k_count<<<(E + 255) / 256, 256>>>(ei, E);
    k_scan<<<1, 1024>>>();
    k_h<<<(N_NODES * 32) / 256, 256>>>(x, W);
    k_scatter<<<(E + 255) / 256, 256>>>(ei, E);
    k_gather<<<(N_NODES * 32) / 256, 256>>>(b);

    dim3 grid(N_NODES / 128, N_NODES / 128);
    k_gemm_sym<<<grid, 256>>>(out);
}